// round 13
// baseline (speedup 1.0000x reference)
#include <cuda_runtime.h>
#include <cuda_fp16.h>
#include <math.h>

#define BB 4
#define NN 10000
#define EE 160000
#define CC 128
#define ITERS 3
#define M_TOTAL (BB * NN)          // 40000 rows
#define TM 64
#define NTILES (M_TOTAL / TM)      // 625
#define LDH 136                    // padded smem stride in halves (272B)
#define THREADS 512
#define PGRID 148
#define STRIDE 128                 // ELL slots per node (mean degree 32)

// ---------------- scratch (static device globals; no runtime allocation) ----
__device__ __align__(16) float  g_EA[M_TOTAL * CC];       // exp(states@Wsa + att_b)
__device__ __align__(16) __half g_T0[M_TOTAL * 2 * CC];   // [EL|ELS] fp16, buffer 0
__device__ __align__(16) __half g_T1[M_TOTAL * 2 * CC];   // [EL|ELS] fp16, buffer 1
__device__ int g_cur[M_TOTAL];                            // degree after fill
__device__ int g_adj[M_TOTAL * STRIDE];                   // ELL adjacency
__device__ int g_tick[8];                                 // per-launch tile tickets

// ---------------- ELL build ------------------------------------------------
__global__ void zero_cur_kernel() {
    int i = blockIdx.x * blockDim.x + threadIdx.x;
    if (i < M_TOTAL) g_cur[i] = 0;
    if (i < 8) g_tick[i] = 0;
}

__global__ void fill_kernel(const int* __restrict__ conn) {
    int idx = blockIdx.x * blockDim.x + threadIdx.x;
    if (idx >= BB * EE) return;
    int b = idx / EE;
    int2 uv = ((const int2*)conn)[idx];
    int nu = b * NN + uv.x, nv = b * NN + uv.y;
    int p = atomicAdd(&g_cur[nu], 1);
    if (p < STRIDE) g_adj[(size_t)nu * STRIDE + p] = uv.y;
    int q = atomicAdd(&g_cur[nv], 1);
    if (q < STRIDE) g_adj[(size_t)nv * STRIDE + q] = uv.x;
}

// ---------------- mma.sync helpers -----------------------------------------
__device__ __forceinline__ unsigned smem_u32(const void* p) {
    return (unsigned)__cvta_generic_to_shared(p);
}

#define LDSM_X4(r0, r1, r2, r3, addr) \
    asm volatile("ldmatrix.sync.aligned.m8n8.x4.shared.b16 {%0,%1,%2,%3}, [%4];" \
                 : "=r"(r0), "=r"(r1), "=r"(r2), "=r"(r3) : "r"(addr))
#define LDSM_X4T(r0, r1, r2, r3, addr) \
    asm volatile("ldmatrix.sync.aligned.m8n8.x4.trans.shared.b16 {%0,%1,%2,%3}, [%4];" \
                 : "=r"(r0), "=r"(r1), "=r"(r2), "=r"(r3) : "r"(addr))
#define MMA16816(acc, a0, a1, a2, a3, b0, b1) \
    asm volatile("mma.sync.aligned.m16n8k16.row.col.f32.f16.f16.f32 " \
                 "{%0,%1,%2,%3}, {%4,%5,%6,%7}, {%8,%9}, {%0,%1,%2,%3};" \
                 : "+f"(acc[0]), "+f"(acc[1]), "+f"(acc[2]), "+f"(acc[3]) \
                 : "r"(a0), "r"(a1), "r"(a2), "r"(a3), "r"(b0), "r"(b1))

// convert one fp32 128x128 weight matrix into fp16 smem (stride LDH)
__device__ __forceinline__ void load_W(const float* __restrict__ W, __half* Ws, int t) {
    const float4* W4 = (const float4*)W;
#pragma unroll
    for (int i = 0; i < 8; i++) {
        float4 v = W4[t + 512 * i];
        int e = (t + 512 * i) * 4;
        int r = e >> 7, c = e & 127;
        __half2* dst = (__half2*)&Ws[r * LDH + c];
        dst[0] = __floats2half2_rn(v.x, v.y);
        dst[1] = __floats2half2_rn(v.z, v.w);
    }
}

__device__ __forceinline__ void acc8_fp16(float* acc, uint4 v) {
    unsigned int u[4] = {v.x, v.y, v.z, v.w};
#pragma unroll
    for (int q = 0; q < 4; q++) {
        float2 f = __half22float2(*(__half2*)&u[q]);
        acc[2 * q]     += f.x;
        acc[2 * q + 1] += f.y;
    }
}

// warp-collective: gather node's neighbors, write G (fp16) and SS (fp32) tiles
__device__ __forceinline__ void gather_node(
    int node, int lrow, int lane,
    const float* __restrict__ states, const float* __restrict__ EA,
    const __half* __restrict__ Tin, __half* Gs, float* SSs)
{
    int b = node / NN;
    int deg = g_cur[node];
    if (deg > STRIDE) deg = STRIDE;
    const int* __restrict__ adj = g_adj + (size_t)node * STRIDE;
    const uint4* __restrict__ T4 = (const uint4*)Tin + (size_t)b * NN * 32;

    float acc[8];
#pragma unroll
    for (int k = 0; k < 8; k++) acc[k] = 0.f;

    int e = 0;
    for (; e + 8 <= deg; e += 8) {          // 8 gathers in flight
        int j[8];
#pragma unroll
        for (int q = 0; q < 8; q++) j[q] = __ldg(adj + e + q);
        uint4 tv[8];
#pragma unroll
        for (int q = 0; q < 8; q++) tv[q] = T4[(size_t)j[q] * 32 + lane];
#pragma unroll
        for (int q = 0; q < 8; q++) acc8_fp16(acc, tv[q]);
    }
    for (; e < deg; e++) {
        int j = __ldg(adj + e);
        uint4 tv = T4[(size_t)j * 32 + lane];
        acc8_fp16(acc, tv);
    }

    float other[8];
#pragma unroll
    for (int k = 0; k < 8; k++)
        other[k] = __shfl_xor_sync(0xffffffffu, acc[k], 16);

    int sub = lane & 15;
    size_t rowf4 = (size_t)node * 32 + sub * 2;
    float4 ea0 = ((const float4*)EA)[rowf4];
    float4 ea1 = ((const float4*)EA)[rowf4 + 1];
    float ea[8] = {ea0.x, ea0.y, ea0.z, ea0.w, ea1.x, ea1.y, ea1.z, ea1.w};

    float sE[8], sS[8];
    if (lane < 16) {
#pragma unroll
        for (int k = 0; k < 8; k++) { sE[k] = acc[k]; sS[k] = other[k]; }
    } else {
#pragma unroll
        for (int k = 0; k < 8; k++) { sE[k] = other[k]; sS[k] = acc[k]; }
    }
    float inv[8];
#pragma unroll
    for (int k = 0; k < 8; k++) inv[k] = 1.f / (1.f + ea[k] * sE[k]);

    if (lane < 16) {
        // G = ea * sS * inv  -> fp16 tile (MMA A operand)
        __half2 h[4];
#pragma unroll
        for (int q = 0; q < 4; q++)
            h[q] = __floats2half2_rn(ea[2 * q] * sS[2 * q] * inv[2 * q],
                                     ea[2 * q + 1] * sS[2 * q + 1] * inv[2 * q + 1]);
        *(uint4*)&Gs[lrow * LDH + sub * 8] = *(uint4*)h;
    } else {
        // SS = states * inv  -> fp32 tile
        float4 st0 = ((const float4*)states)[rowf4];
        float4 st1 = ((const float4*)states)[rowf4 + 1];
        float4 S0, S1;
        S0.x = st0.x * inv[0]; S0.y = st0.y * inv[1];
        S0.z = st0.z * inv[2]; S0.w = st0.w * inv[3];
        S1.x = st1.x * inv[4]; S1.y = st1.y * inv[5];
        S1.z = st1.z * inv[6]; S1.w = st1.w * inv[7];
        *(float4*)&SSs[lrow * CC + sub * 8]     = S0;
        *(float4*)&SSs[lrow * CC + sub * 8 + 4] = S1;
    }
}

// ---------------- init kernel: states = tanh(objects@Wos + b); + attention -
__global__ void __launch_bounds__(THREADS, 1)
init_k(const float* __restrict__ X, const float* __restrict__ W0,
       const float* __restrict__ stb,
       const float* __restrict__ W1, const float* __restrict__ W2,
       const float* __restrict__ attb,
       float* __restrict__ states, float* __restrict__ EA, __half* __restrict__ Tout)
{
    extern __shared__ __half sh[];
    __half* W0s = sh;
    __half* W1s = sh + CC * LDH;
    __half* W2s = sh + 2 * CC * LDH;
    __half* Xs  = sh + 3 * CC * LDH;     // TM x LDH
    __half* Ss  = Xs + TM * LDH;         // TM x LDH
    __shared__ int s_tile;
    int t = threadIdx.x, lane = t & 31, wid = t >> 5;

    load_W(W0, W0s, t);
    load_W(W1, W1s, t);
    load_W(W2, W2s, t);

    int wm = (wid & 3) * 16, wn = (wid >> 2) * 32;
    int a_row = wm + (lane & 15), a_koff = (lane >> 4) << 3;
    int b_krow = ((lane >> 3) & 1) * 8 + (lane & 7), b_noff = (lane >> 4) << 3;
    int lr0 = wm + (lane >> 2), col_in = (lane & 3) * 2;

    int tile = blockIdx.x;
    while (tile < NTILES) {
        const float4* X4 = (const float4*)(X + (size_t)tile * TM * CC);
#pragma unroll
        for (int i = 0; i < 4; i++) {
            float4 v = X4[t + 512 * i];
            int e = (t + 512 * i) * 4;
            int r = e >> 7, c = e & 127;
            __half2* dst = (__half2*)&Xs[r * LDH + c];
            dst[0] = __floats2half2_rn(v.x, v.y);
            dst[1] = __floats2half2_rn(v.z, v.w);
        }
        __syncthreads();

        float acc[4][4];
#pragma unroll
        for (int nf = 0; nf < 4; nf++)
#pragma unroll
            for (int q = 0; q < 4; q++) acc[nf][q] = 0.f;
#pragma unroll
        for (int ks = 0; ks < 8; ks++) {
            int kk = ks * 16;
            unsigned a0, a1, a2, a3;
            LDSM_X4(a0, a1, a2, a3, smem_u32(&Xs[a_row * LDH + kk + a_koff]));
#pragma unroll
            for (int nf = 0; nf < 4; nf += 2) {
                unsigned b0, b1, b2, b3;
                LDSM_X4T(b0, b1, b2, b3, smem_u32(&W0s[(kk + b_krow) * LDH + wn + nf * 8 + b_noff]));
                MMA16816(acc[nf],     a0, a1, a2, a3, b0, b1);
                MMA16816(acc[nf + 1], a0, a1, a2, a3, b2, b3);
            }
        }
#pragma unroll
        for (int nf = 0; nf < 4; nf++) {
            int col = wn + nf * 8 + col_in;
#pragma unroll
            for (int h = 0; h < 2; h++) {
                int lrow = lr0 + h * 8;
                size_t grow = (size_t)(tile * TM + lrow);
                float2 bz = *(const float2*)&stb[col];
                float s0 = tanhf(acc[nf][h * 2 + 0] + bz.x);
                float s1 = tanhf(acc[nf][h * 2 + 1] + bz.y);
                float2 o; o.x = s0; o.y = s1;
                *(float2*)&states[grow * CC + col] = o;
                *(__half2*)&Ss[lrow * LDH + col] = __floats2half2_rn(s0, s1);
            }
        }
        __syncthreads();

        float accE[4][4], accL[4][4];
#pragma unroll
        for (int nf = 0; nf < 4; nf++)
#pragma unroll
            for (int q = 0; q < 4; q++) { accE[nf][q] = 0.f; accL[nf][q] = 0.f; }
#pragma unroll
        for (int ks = 0; ks < 8; ks++) {
            int kk = ks * 16;
            unsigned a0, a1, a2, a3;
            LDSM_X4(a0, a1, a2, a3, smem_u32(&Ss[a_row * LDH + kk + a_koff]));
#pragma unroll
            for (int nf = 0; nf < 4; nf += 2) {
                unsigned b0, b1, b2, b3;
                LDSM_X4T(b0, b1, b2, b3, smem_u32(&W1s[(kk + b_krow) * LDH + wn + nf * 8 + b_noff]));
                MMA16816(accE[nf],     a0, a1, a2, a3, b0, b1);
                MMA16816(accE[nf + 1], a0, a1, a2, a3, b2, b3);
                LDSM_X4T(b0, b1, b2, b3, smem_u32(&W2s[(kk + b_krow) * LDH + wn + nf * 8 + b_noff]));
                MMA16816(accL[nf],     a0, a1, a2, a3, b0, b1);
                MMA16816(accL[nf + 1], a0, a1, a2, a3, b2, b3);
            }
        }
#pragma unroll
        for (int nf = 0; nf < 4; nf++) {
            int col = wn + nf * 8 + col_in;
#pragma unroll
            for (int h = 0; h < 2; h++) {
                int lrow = lr0 + h * 8;
                size_t grow = (size_t)(tile * TM + lrow);
                float2 bz = *(const float2*)&attb[col];
                float2 oe;
                oe.x = __expf(accE[nf][h * 2 + 0] + bz.x);
                oe.y = __expf(accE[nf][h * 2 + 1] + bz.y);
                *(float2*)&EA[grow * CC + col] = oe;
                float el0 = __expf(accL[nf][h * 2 + 0]);
                float el1 = __expf(accL[nf][h * 2 + 1]);
                float s0 = __half2float(Ss[lrow * LDH + col]);
                float s1 = __half2float(Ss[lrow * LDH + col + 1]);
                *(__half2*)&Tout[grow * 2 * CC + col]      = __floats2half2_rn(el0, el1);
                *(__half2*)&Tout[grow * 2 * CC + CC + col] = __floats2half2_rn(el0 * s0, el1 * s1);
            }
        }

        if (t == 0) s_tile = gridDim.x + atomicAdd(&g_tick[0], 1);
        __syncthreads();
        tile = s_tile;
    }
}

// ---------------- fused iteration kernel: agg + update (+ attention) -------
template <int DO_ATTN>
__global__ void __launch_bounds__(THREADS, 1)
iter_k(float* states,                         // in: prev (row-local), out: new
       const float* __restrict__ Wl, const float* __restrict__ stb,
       const float* __restrict__ W1, const float* __restrict__ W2,
       const float* __restrict__ attb,
       float* __restrict__ EA,
       const __half* __restrict__ Tin, __half* __restrict__ Tout, int slot)
{
    extern __shared__ __half sh[];
    const int WOFF = DO_ATTN ? 3 : 1;
    __half* Wls = sh;
    __half* W1s = sh + CC * LDH;              // valid only when DO_ATTN
    __half* W2s = sh + 2 * CC * LDH;
    __half* Gs  = sh + WOFF * CC * LDH;       // TM x LDH
    __half* Ss  = Gs + TM * LDH;              // TM x LDH (DO_ATTN only)
    float*  SSs = (float*)(Gs + 2 * TM * LDH);// TM x CC fp32
    __shared__ int s_tile;
    int t = threadIdx.x, lane = t & 31, wid = t >> 5;

    load_W(Wl, Wls, t);
    if (DO_ATTN) {
        load_W(W1, W1s, t);
        load_W(W2, W2s, t);
    }

    int wm = (wid & 3) * 16, wn = (wid >> 2) * 32;
    int a_row = wm + (lane & 15), a_koff = (lane >> 4) << 3;
    int b_krow = ((lane >> 3) & 1) * 8 + (lane & 7), b_noff = (lane >> 4) << 3;
    int lr0 = wm + (lane >> 2), col_in = (lane & 3) * 2;

    int tile = blockIdx.x;
    while (tile < NTILES) {
        // ---- gather: each of 16 warps handles 4 nodes
#pragma unroll 1
        for (int nn = 0; nn < 4; nn++) {
            int lrow = wid * 4 + nn;
            gather_node(tile * TM + lrow, lrow, lane, states, EA, Tin, Gs, SSs);
        }
        __syncthreads();

        // ---- update GEMM: S = tanh(G @ Wl + SS + stb)
        float acc[4][4];
#pragma unroll
        for (int nf = 0; nf < 4; nf++)
#pragma unroll
            for (int q = 0; q < 4; q++) acc[nf][q] = 0.f;
#pragma unroll
        for (int ks = 0; ks < 8; ks++) {
            int kk = ks * 16;
            unsigned a0, a1, a2, a3;
            LDSM_X4(a0, a1, a2, a3, smem_u32(&Gs[a_row * LDH + kk + a_koff]));
#pragma unroll
            for (int nf = 0; nf < 4; nf += 2) {
                unsigned b0, b1, b2, b3;
                LDSM_X4T(b0, b1, b2, b3, smem_u32(&Wls[(kk + b_krow) * LDH + wn + nf * 8 + b_noff]));
                MMA16816(acc[nf],     a0, a1, a2, a3, b0, b1);
                MMA16816(acc[nf + 1], a0, a1, a2, a3, b2, b3);
            }
        }
#pragma unroll
        for (int nf = 0; nf < 4; nf++) {
            int col = wn + nf * 8 + col_in;
#pragma unroll
            for (int h = 0; h < 2; h++) {
                int lrow = lr0 + h * 8;
                size_t grow = (size_t)(tile * TM + lrow);
                float2 bz = *(const float2*)&stb[col];
                float v0 = acc[nf][h * 2 + 0] + SSs[lrow * CC + col]     + bz.x;
                float v1 = acc[nf][h * 2 + 1] + SSs[lrow * CC + col + 1] + bz.y;
                float s0 = tanhf(v0), s1 = tanhf(v1);
                float2 o; o.x = s0; o.y = s1;
                *(float2*)&states[grow * CC + col] = o;
                if (DO_ATTN) *(__half2*)&Ss[lrow * LDH + col] = __floats2half2_rn(s0, s1);
            }
        }

        if (DO_ATTN) {
            __syncthreads();
            float accE[4][4], accL[4][4];
#pragma unroll
            for (int nf = 0; nf < 4; nf++)
#pragma unroll
                for (int q = 0; q < 4; q++) { accE[nf][q] = 0.f; accL[nf][q] = 0.f; }
#pragma unroll
            for (int ks = 0; ks < 8; ks++) {
                int kk = ks * 16;
                unsigned a0, a1, a2, a3;
                LDSM_X4(a0, a1, a2, a3, smem_u32(&Ss[a_row * LDH + kk + a_koff]));
#pragma unroll
                for (int nf = 0; nf < 4; nf += 2) {
                    unsigned b0, b1, b2, b3;
                    LDSM_X4T(b0, b1, b2, b3, smem_u32(&W1s[(kk + b_krow) * LDH + wn + nf * 8 + b_noff]));
                    MMA16816(accE[nf],     a0, a1, a2, a3, b0, b1);
                    MMA16816(accE[nf + 1], a0, a1, a2, a3, b2, b3);
                    LDSM_X4T(b0, b1, b2, b3, smem_u32(&W2s[(kk + b_krow) * LDH + wn + nf * 8 + b_noff]));
                    MMA16816(accL[nf],     a0, a1, a2, a3, b0, b1);
                    MMA16816(accL[nf + 1], a0, a1, a2, a3, b2, b3);
                }
            }
#pragma unroll
            for (int nf = 0; nf < 4; nf++) {
                int col = wn + nf * 8 + col_in;
#pragma unroll
                for (int h = 0; h < 2; h++) {
                    int lrow = lr0 + h * 8;
                    size_t grow = (size_t)(tile * TM + lrow);
                    float2 bz = *(const float2*)&attb[col];
                    float2 oe;
                    oe.x = __expf(accE[nf][h * 2 + 0] + bz.x);
                    oe.y = __expf(accE[nf][h * 2 + 1] + bz.y);
                    *(float2*)&EA[grow * CC + col] = oe;
                    float el0 = __expf(accL[nf][h * 2 + 0]);
                    float el1 = __expf(accL[nf][h * 2 + 1]);
                    float s0 = __half2float(Ss[lrow * LDH + col]);
                    float s1 = __half2float(Ss[lrow * LDH + col + 1]);
                    *(__half2*)&Tout[grow * 2 * CC + col]      = __floats2half2_rn(el0, el1);
                    *(__half2*)&Tout[grow * 2 * CC + CC + col] = __floats2half2_rn(el0 * s0, el1 * s1);
                }
            }
        }

        if (t == 0) s_tile = gridDim.x + atomicAdd(&g_tick[slot], 1);
        __syncthreads();
        tile = s_tile;
    }
}

// ---------------- launch ----------------------------------------------------
extern "C" void kernel_launch(void* const* d_in, const int* in_sizes, int n_in,
                              void* d_out, int out_size) {
    const float* objects = (const float*)d_in[0];
    const float* Wos     = (const float*)d_in[1];
    const float* Wsa     = (const float*)d_in[2];
    const float* Wla     = (const float*)d_in[3];
    const float* att_b   = (const float*)d_in[4];
    const float* Wl      = (const float*)d_in[5];
    const float* st_b    = (const float*)d_in[6];
    const int*   conn    = (const int*)d_in[7];
    float* states = (float*)d_out;            // live states buffer, [B,N,C]

    const size_t SM_INIT = (size_t)(3 * CC * LDH + 2 * TM * LDH) * 2;              // 139264
    const size_t SM_IT1  = (size_t)(3 * CC * LDH + 2 * TM * LDH) * 2 + TM * CC * 4; // 172032
    const size_t SM_IT0  = (size_t)(1 * CC * LDH + 2 * TM * LDH) * 2 + TM * CC * 4; // 102400

    cudaFuncSetAttribute(init_k,    cudaFuncAttributeMaxDynamicSharedMemorySize, (int)SM_INIT);
    cudaFuncSetAttribute(iter_k<1>, cudaFuncAttributeMaxDynamicSharedMemorySize, (int)SM_IT1);
    cudaFuncSetAttribute(iter_k<0>, cudaFuncAttributeMaxDynamicSharedMemorySize, (int)SM_IT0);

    float* pEA;
    __half *pT0, *pT1;
    cudaGetSymbolAddress((void**)&pEA, g_EA);
    cudaGetSymbolAddress((void**)&pT0, g_T0);
    cudaGetSymbolAddress((void**)&pT1, g_T1);

    const int EDGE_BLOCKS = (BB * EE + 255) / 256;      // 2500

    // ELL build + ticket reset (per launch; connections are an input)
    zero_cur_kernel<<<(M_TOTAL + 255) / 256, 256>>>();
    fill_kernel<<<EDGE_BLOCKS, 256>>>(conn);

    // iter 0: init states + attention tables (into T0)
    init_k<<<PGRID, THREADS, SM_INIT>>>(objects, Wos, st_b, Wsa, Wla, att_b,
                                        states, pEA, pT0);
    // iters 1..2: fused agg+update+attention (ping-pong T)
    iter_k<1><<<PGRID, THREADS, SM_IT1>>>(states, Wl, st_b, Wsa, Wla, att_b,
                                          pEA, pT0, pT1, 1);
    iter_k<1><<<PGRID, THREADS, SM_IT1>>>(states, Wl, st_b, Wsa, Wla, att_b,
                                          pEA, pT1, pT0, 2);
    // final iter: agg+update only (smaller smem -> 2 CTAs/SM for more MLP)
    iter_k<0><<<2 * PGRID, THREADS, SM_IT0>>>(states, Wl, st_b, Wsa, Wla, att_b,
                                              pEA, pT0, pT1, 3);
}

// round 14
// speedup vs baseline: 1.3470x; 1.3470x over previous
#include <cuda_runtime.h>
#include <cuda_fp16.h>
#include <math.h>

#define BB 4
#define NN 10000
#define EE 160000
#define CC 128
#define ITERS 3
#define M_TOTAL (BB * NN)          // 40000 rows
#define TM 64
#define NTILES (M_TOTAL / TM)      // 625
#define LDH 136                    // padded smem stride in halves (272B)
#define GEMM_THREADS 512
#define GEMM_SMEM_BYTES ((TM + CC) * LDH * 2)        // 52224 B
#define GEMM12_SMEM_BYTES ((TM + 2 * CC) * LDH * 2)  // 87040 B
#define PGRID 148                  // persistent grid: one CTA per SM
#define STRIDE 128                 // ELL slots per node (mean degree 32)

// ---------------- scratch (static device globals; no runtime allocation) ----
__device__ __align__(16) float g_EA [M_TOTAL * CC];      // exp(states@Wsa + att_b)
__device__ __align__(16) __half g_T[M_TOTAL * 2 * CC];   // per node: [EL(128) | ELS(128)] fp16
__device__ __align__(16) float g_G  [M_TOTAL * CC];      // linked_gated
__device__ __align__(16) float g_SS [M_TOTAL * CC];      // states / norm
__device__ int g_cur[M_TOTAL];                           // fill cursor == degree after fill
__device__ int g_adj[M_TOTAL * STRIDE];                  // ELL adjacency

// ---------------- ELL build ------------------------------------------------
__global__ void zero_cur_kernel() {
    int i = blockIdx.x * blockDim.x + threadIdx.x;
    if (i < M_TOTAL) g_cur[i] = 0;
}

__global__ void fill_kernel(const int* __restrict__ conn) {
    int idx = blockIdx.x * blockDim.x + threadIdx.x;
    if (idx >= BB * EE) return;
    int b = idx / EE;
    int2 uv = ((const int2*)conn)[idx];
    int nu = b * NN + uv.x, nv = b * NN + uv.y;
    int p = atomicAdd(&g_cur[nu], 1);
    if (p < STRIDE) g_adj[(size_t)nu * STRIDE + p] = uv.y;
    int q = atomicAdd(&g_cur[nv], 1);
    if (q < STRIDE) g_adj[(size_t)nv * STRIDE + q] = uv.x;
}

// ---------------- mma.sync helpers -----------------------------------------
__device__ __forceinline__ unsigned smem_u32(const void* p) {
    return (unsigned)__cvta_generic_to_shared(p);
}

#define LDSM_X4(r, addr) \
    asm volatile("ldmatrix.sync.aligned.m8n8.x4.shared.b16 {%0,%1,%2,%3}, [%4];" \
                 : "=r"((r)[0]), "=r"((r)[1]), "=r"((r)[2]), "=r"((r)[3]) : "r"(addr))
#define LDSM_X4T(r, addr) \
    asm volatile("ldmatrix.sync.aligned.m8n8.x4.trans.shared.b16 {%0,%1,%2,%3}, [%4];" \
                 : "=r"((r)[0]), "=r"((r)[1]), "=r"((r)[2]), "=r"((r)[3]) : "r"(addr))
#define MMA16816(acc, a, b0, b1) \
    asm volatile("mma.sync.aligned.m16n8k16.row.col.f32.f16.f16.f32 " \
                 "{%0,%1,%2,%3}, {%4,%5,%6,%7}, {%8,%9}, {%0,%1,%2,%3};" \
                 : "+f"((acc)[0]), "+f"((acc)[1]), "+f"((acc)[2]), "+f"((acc)[3]) \
                 : "r"((a)[0]), "r"((a)[1]), "r"((a)[2]), "r"((a)[3]), "r"(b0), "r"(b1))

#define KSTEP_A (16 * 2)            // 16 halves per k-step (A row direction)
#define KSTEP_B (16 * LDH * 2)      // 16 rows per k-step (B k direction)

// store 4 float4 (one X row-chunk per thread) into fp16 smem tile
__device__ __forceinline__ void stash_X(__half* As, const float4* rX, int t) {
#pragma unroll
    for (int i = 0; i < 4; i++) {
        int e = (t + 512 * i) * 4;
        int r = e >> 7, c = e & 127;
        __half2* dst = (__half2*)&As[r * LDH + c];
        dst[0] = __floats2half2_rn(rX[i].x, rX[i].y);
        dst[1] = __floats2half2_rn(rX[i].z, rX[i].w);
    }
}

// ---------------- persistent GEMM [40000,128]x[128,128], pipelined ---------
// MODE 0: O1 = tanh(acc + bias)       MODE 3: O1 = tanh(acc + add + bias)
template <int MODE>
__global__ void __launch_bounds__(GEMM_THREADS, 1)
gemm_k(const float* __restrict__ X, const float* __restrict__ W,
       const float* __restrict__ bias, const float* __restrict__ add,
       float* __restrict__ O1) {
    extern __shared__ __half sh[];
    __half* As  = sh;                 // TM x LDH
    __half* Wsh = sh + TM * LDH;      // CC x LDH
    int t = threadIdx.x;

    const float4* W4 = (const float4*)W;
#pragma unroll
    for (int i = 0; i < 8; i++) {
        float4 v = W4[t + 512 * i];
        int e = (t + 512 * i) * 4;
        int r = e >> 7, c = e & 127;
        __half2* dst = (__half2*)&Wsh[r * LDH + c];
        dst[0] = __floats2half2_rn(v.x, v.y);
        dst[1] = __floats2half2_rn(v.z, v.w);
    }

    int lane = t & 31, wid = t >> 5;
    int wm = (wid & 3) * 16;
    int wn = (wid >> 2) * 32;
    unsigned a_base  = smem_u32(&As[(wm + (lane & 15)) * LDH + ((lane >> 4) << 3)]);
    unsigned b_base  = smem_u32(&Wsh[(((lane >> 3) & 1) * 8 + (lane & 7)) * LDH
                                     + wn + ((lane >> 4) << 3)]);
    int lr0 = wm + (lane >> 2);
    int col_in = (lane & 3) * 2;

    float4 rX[4];
    int tile = blockIdx.x;
    if (tile < NTILES) {
        const float4* X4 = (const float4*)(X + (size_t)tile * TM * CC);
#pragma unroll
        for (int i = 0; i < 4; i++) rX[i] = X4[t + 512 * i];
    }

    for (; tile < NTILES; tile += PGRID) {
        __syncthreads();
        stash_X(As, rX, t);
        __syncthreads();

        float acc[4][4];
#pragma unroll
        for (int nf = 0; nf < 4; nf++)
#pragma unroll
            for (int q = 0; q < 4; q++) acc[nf][q] = 0.f;

        unsigned a[2][4], b0[2][4], b1[2][4];
        LDSM_X4 (a[0],  a_base);
        LDSM_X4T(b0[0], b_base);
        LDSM_X4T(b1[0], b_base + 32);
#pragma unroll
        for (int ks = 0; ks < 8; ks++) {
            int cur = ks & 1, nxt = cur ^ 1;
            if (ks < 7) {
                unsigned ao = a_base + (ks + 1) * KSTEP_A;
                unsigned bo = b_base + (ks + 1) * KSTEP_B;
                LDSM_X4 (a[nxt],  ao);
                LDSM_X4T(b0[nxt], bo);
                LDSM_X4T(b1[nxt], bo + 32);
            }
            MMA16816(acc[0], a[cur], b0[cur][0], b0[cur][1]);
            MMA16816(acc[1], a[cur], b0[cur][2], b0[cur][3]);
            MMA16816(acc[2], a[cur], b1[cur][0], b1[cur][1]);
            MMA16816(acc[3], a[cur], b1[cur][2], b1[cur][3]);
        }

        int next = tile + PGRID;
        if (next < NTILES) {
            const float4* X4 = (const float4*)(X + (size_t)next * TM * CC);
#pragma unroll
            for (int i = 0; i < 4; i++) rX[i] = X4[t + 512 * i];
        }

        int block_row = tile * TM;
#pragma unroll
        for (int nf = 0; nf < 4; nf++) {
            int col = wn + nf * 8 + col_in;
#pragma unroll
            for (int half = 0; half < 2; half++) {
                int lrow = lr0 + half * 8;
                size_t grow = (size_t)(block_row + lrow);
                float v0 = acc[nf][half * 2 + 0];
                float v1 = acc[nf][half * 2 + 1];
                float2 bz = *(const float2*)&bias[col];
                if (MODE == 3) {
                    float2 ad = *(const float2*)&add[grow * CC + col];
                    v0 += ad.x; v1 += ad.y;
                }
                float2 o;
                o.x = tanhf(v0 + bz.x);
                o.y = tanhf(v1 + bz.y);
                *(float2*)&O1[grow * CC + col] = o;
            }
        }
    }
}

// ---------------- persistent fused EA + EL/ELS GEMM, pipelined -------------
__global__ void __launch_bounds__(GEMM_THREADS, 1)
gemm12_k(const float* __restrict__ X,
         const float* __restrict__ W1,   // state_attention_W -> EA
         const float* __restrict__ W2,   // linked_state_attention_W -> EL
         const float* __restrict__ attb,
         float* __restrict__ OEA, __half* __restrict__ OT) {
    extern __shared__ __half sh[];
    __half* As  = sh;                      // TM x LDH
    __half* W1s = sh + TM * LDH;           // CC x LDH
    __half* W2s = sh + (TM + CC) * LDH;    // CC x LDH
    int t = threadIdx.x;

    const float4* W14 = (const float4*)W1;
    const float4* W24 = (const float4*)W2;
#pragma unroll
    for (int i = 0; i < 8; i++) {
        float4 v = W14[t + 512 * i];
        int e = (t + 512 * i) * 4;
        int r = e >> 7, c = e & 127;
        __half2* dst = (__half2*)&W1s[r * LDH + c];
        dst[0] = __floats2half2_rn(v.x, v.y);
        dst[1] = __floats2half2_rn(v.z, v.w);
        float4 u = W24[t + 512 * i];
        __half2* dst2 = (__half2*)&W2s[r * LDH + c];
        dst2[0] = __floats2half2_rn(u.x, u.y);
        dst2[1] = __floats2half2_rn(u.z, u.w);
    }

    int lane = t & 31, wid = t >> 5;
    int wm = (wid & 3) * 16;
    int wn = (wid >> 2) * 32;
    unsigned a_base  = smem_u32(&As[(wm + (lane & 15)) * LDH + ((lane >> 4) << 3)]);
    int brow = ((lane >> 3) & 1) * 8 + (lane & 7);
    unsigned b1_base = smem_u32(&W1s[brow * LDH + wn + ((lane >> 4) << 3)]);
    unsigned b2_base = smem_u32(&W2s[brow * LDH + wn + ((lane >> 4) << 3)]);
    int lr0 = wm + (lane >> 2);
    int col_in = (lane & 3) * 2;

    float4 rX[4];
    int tile = blockIdx.x;
    if (tile < NTILES) {
        const float4* X4 = (const float4*)(X + (size_t)tile * TM * CC);
#pragma unroll
        for (int i = 0; i < 4; i++) rX[i] = X4[t + 512 * i];
    }

    for (; tile < NTILES; tile += PGRID) {
        __syncthreads();
        stash_X(As, rX, t);
        __syncthreads();

        float accE[4][4], accL[4][4];
#pragma unroll
        for (int nf = 0; nf < 4; nf++)
#pragma unroll
            for (int q = 0; q < 4; q++) { accE[nf][q] = 0.f; accL[nf][q] = 0.f; }

        unsigned a[2][4], bE0[2][4], bE1[2][4], bL0[2][4], bL1[2][4];
        LDSM_X4 (a[0],   a_base);
        LDSM_X4T(bE0[0], b1_base);
        LDSM_X4T(bE1[0], b1_base + 32);
        LDSM_X4T(bL0[0], b2_base);
        LDSM_X4T(bL1[0], b2_base + 32);
#pragma unroll
        for (int ks = 0; ks < 8; ks++) {
            int cur = ks & 1, nxt = cur ^ 1;
            if (ks < 7) {
                unsigned ao = a_base + (ks + 1) * KSTEP_A;
                unsigned b1o = b1_base + (ks + 1) * KSTEP_B;
                unsigned b2o = b2_base + (ks + 1) * KSTEP_B;
                LDSM_X4 (a[nxt],   ao);
                LDSM_X4T(bE0[nxt], b1o);
                LDSM_X4T(bE1[nxt], b1o + 32);
                LDSM_X4T(bL0[nxt], b2o);
                LDSM_X4T(bL1[nxt], b2o + 32);
            }
            MMA16816(accE[0], a[cur], bE0[cur][0], bE0[cur][1]);
            MMA16816(accE[1], a[cur], bE0[cur][2], bE0[cur][3]);
            MMA16816(accE[2], a[cur], bE1[cur][0], bE1[cur][1]);
            MMA16816(accE[3], a[cur], bE1[cur][2], bE1[cur][3]);
            MMA16816(accL[0], a[cur], bL0[cur][0], bL0[cur][1]);
            MMA16816(accL[1], a[cur], bL0[cur][2], bL0[cur][3]);
            MMA16816(accL[2], a[cur], bL1[cur][0], bL1[cur][1]);
            MMA16816(accL[3], a[cur], bL1[cur][2], bL1[cur][3]);
        }

        int next = tile + PGRID;
        if (next < NTILES) {
            const float4* X4 = (const float4*)(X + (size_t)next * TM * CC);
#pragma unroll
            for (int i = 0; i < 4; i++) rX[i] = X4[t + 512 * i];
        }

        int block_row = tile * TM;
#pragma unroll
        for (int nf = 0; nf < 4; nf++) {
            int col = wn + nf * 8 + col_in;
#pragma unroll
            for (int half = 0; half < 2; half++) {
                int lrow = lr0 + half * 8;
                size_t grow = (size_t)(block_row + lrow);
                // EA
                float2 bz = *(const float2*)&attb[col];
                float2 oe;
                oe.x = __expf(accE[nf][half * 2 + 0] + bz.x);
                oe.y = __expf(accE[nf][half * 2 + 1] + bz.y);
                *(float2*)&OEA[grow * CC + col] = oe;
                // EL / ELS (states read from As)
                float el0 = __expf(accL[nf][half * 2 + 0]);
                float el1 = __expf(accL[nf][half * 2 + 1]);
                float s0 = __half2float(As[lrow * LDH + col]);
                float s1 = __half2float(As[lrow * LDH + col + 1]);
                __half2 e  = __floats2half2_rn(el0, el1);
                __half2 es = __floats2half2_rn(el0 * s0, el1 * s1);
                *(__half2*)&OT[grow * 2 * CC + col]      = e;
                *(__half2*)&OT[grow * 2 * CC + CC + col] = es;
            }
        }
    }
}

// ---------------- per-node aggregation (one warp per node, no atomics) -----
__device__ __forceinline__ void acc8_fp16(float* acc, uint4 v) {
    unsigned int u[4] = {v.x, v.y, v.z, v.w};
#pragma unroll
    for (int q = 0; q < 4; q++) {
        float2 f = __half22float2(*(__half2*)&u[q]);
        acc[2 * q]     += f.x;
        acc[2 * q + 1] += f.y;
    }
}

__global__ void agg_kernel(const float* __restrict__ states) {
    int gw = (blockIdx.x * blockDim.x + threadIdx.x) >> 5;
    int lane = threadIdx.x & 31;
    if (gw >= M_TOTAL) return;
    int b = gw / NN;

    int deg = g_cur[gw];
    if (deg > STRIDE) deg = STRIDE;
    const int* __restrict__ adj = g_adj + (size_t)gw * STRIDE;
    const uint4* __restrict__ T4 = (const uint4*)(g_T + (size_t)b * NN * 2 * CC);

    float acc[8];
#pragma unroll
    for (int k = 0; k < 8; k++) acc[k] = 0.f;

    int e = 0;
    for (; e + 4 <= deg; e += 4) {
        int j0 = __ldg(adj + e);
        int j1 = __ldg(adj + e + 1);
        int j2 = __ldg(adj + e + 2);
        int j3 = __ldg(adj + e + 3);
        uint4 t0 = T4[(size_t)j0 * 32 + lane];
        uint4 t1 = T4[(size_t)j1 * 32 + lane];
        uint4 t2 = T4[(size_t)j2 * 32 + lane];
        uint4 t3 = T4[(size_t)j3 * 32 + lane];
        acc8_fp16(acc, t0);
        acc8_fp16(acc, t1);
        acc8_fp16(acc, t2);
        acc8_fp16(acc, t3);
    }
    for (; e < deg; e++) {
        int j = __ldg(adj + e);
        uint4 tv = T4[(size_t)j * 32 + lane];
        acc8_fp16(acc, tv);
    }

    float other[8];
#pragma unroll
    for (int k = 0; k < 8; k++)
        other[k] = __shfl_xor_sync(0xffffffffu, acc[k], 16);

    int sub = lane & 15;
    size_t rowf4 = (size_t)gw * 32 + sub * 2;
    float4 ea0 = ((const float4*)g_EA)[rowf4];
    float4 ea1 = ((const float4*)g_EA)[rowf4 + 1];
    float ea[8] = {ea0.x, ea0.y, ea0.z, ea0.w, ea1.x, ea1.y, ea1.z, ea1.w};

    float sE[8], sS[8];
    if (lane < 16) {
#pragma unroll
        for (int k = 0; k < 8; k++) { sE[k] = acc[k]; sS[k] = other[k]; }
    } else {
#pragma unroll
        for (int k = 0; k < 8; k++) { sE[k] = other[k]; sS[k] = acc[k]; }
    }

    float inv[8];
#pragma unroll
    for (int k = 0; k < 8; k++) inv[k] = 1.f / (1.f + ea[k] * sE[k]);

    if (lane < 16) {
        float4 G0, G1;
        G0.x = ea[0] * sS[0] * inv[0]; G0.y = ea[1] * sS[1] * inv[1];
        G0.z = ea[2] * sS[2] * inv[2]; G0.w = ea[3] * sS[3] * inv[3];
        G1.x = ea[4] * sS[4] * inv[4]; G1.y = ea[5] * sS[5] * inv[5];
        G1.z = ea[6] * sS[6] * inv[6]; G1.w = ea[7] * sS[7] * inv[7];
        ((float4*)g_G)[rowf4]     = G0;
        ((float4*)g_G)[rowf4 + 1] = G1;
    } else {
        float4 st0 = ((const float4*)states)[rowf4];
        float4 st1 = ((const float4*)states)[rowf4 + 1];
        float4 S0, S1;
        S0.x = st0.x * inv[0]; S0.y = st0.y * inv[1];
        S0.z = st0.z * inv[2]; S0.w = st0.w * inv[3];
        S1.x = st1.x * inv[4]; S1.y = st1.y * inv[5];
        S1.z = st1.z * inv[6]; S1.w = st1.w * inv[7];
        ((float4*)g_SS)[rowf4]     = S0;
        ((float4*)g_SS)[rowf4 + 1] = S1;
    }
}

// ---------------- launch ----------------------------------------------------
extern "C" void kernel_launch(void* const* d_in, const int* in_sizes, int n_in,
                              void* d_out, int out_size) {
    const float* objects = (const float*)d_in[0];
    const float* Wos     = (const float*)d_in[1];
    const float* Wsa     = (const float*)d_in[2];
    const float* Wla     = (const float*)d_in[3];
    const float* att_b   = (const float*)d_in[4];
    const float* Wl      = (const float*)d_in[5];
    const float* st_b    = (const float*)d_in[6];
    const int*   conn    = (const int*)d_in[7];
    float* states = (float*)d_out;            // live states buffer, [B,N,C]

    cudaFuncSetAttribute(gemm_k<0>, cudaFuncAttributeMaxDynamicSharedMemorySize, GEMM_SMEM_BYTES);
    cudaFuncSetAttribute(gemm_k<3>, cudaFuncAttributeMaxDynamicSharedMemorySize, GEMM_SMEM_BYTES);
    cudaFuncSetAttribute(gemm12_k, cudaFuncAttributeMaxDynamicSharedMemorySize, GEMM12_SMEM_BYTES);

    float *pEA, *pG, *pSS;
    __half* pT;
    cudaGetSymbolAddress((void**)&pEA, g_EA);
    cudaGetSymbolAddress((void**)&pT,  g_T);
    cudaGetSymbolAddress((void**)&pG,  g_G);
    cudaGetSymbolAddress((void**)&pSS, g_SS);

    const int EDGE_BLOCKS = (BB * EE + 255) / 256;      // 2500
    const int AGG_GRID    = (M_TOTAL * 32 + 255) / 256; // 5000

    // ELL build (per launch; connections are an input)
    zero_cur_kernel<<<(M_TOTAL + 255) / 256, 256>>>();
    fill_kernel<<<EDGE_BLOCKS, 256>>>(conn);

    // init states = tanh(objects @ Wos + st_b)
    gemm_k<0><<<PGRID, GEMM_THREADS, GEMM_SMEM_BYTES>>>(objects, Wos, st_b, nullptr, states);

    for (int it = 0; it < ITERS; it++) {
        gemm12_k<<<PGRID, GEMM_THREADS, GEMM12_SMEM_BYTES>>>(states, Wsa, Wla, att_b, pEA, pT);
        agg_kernel<<<AGG_GRID, 256>>>(states);
        gemm_k<3><<<PGRID, GEMM_THREADS, GEMM_SMEM_BYTES>>>(pG, Wl, st_b, pSS, states);
    }
}

// round 15
// speedup vs baseline: 1.3675x; 1.0152x over previous
#include <cuda_runtime.h>
#include <cuda_fp16.h>
#include <math.h>

#define BB 4
#define NN 10000
#define EE 160000
#define CC 128
#define ITERS 3
#define M_TOTAL (BB * NN)          // 40000 rows
#define TM 64
#define NTILES (M_TOTAL / TM)      // 625
#define LDH 136                    // padded smem stride in halves (272B)
#define THREADS 512
#define PGRID 148                  // persistent grid: one CTA per SM
#define STRIDE 128                 // ELL slots per node (mean degree 32)

#define SM_FULL ((3 * CC * LDH + 2 * TM * LDH) * 2)   // 139264 B
#define SM_UPD  ((CC * LDH + TM * LDH) * 2)           // 52224 B

// ---------------- scratch (static device globals; no runtime allocation) ----
__device__ __align__(16) float  g_EA[M_TOTAL * CC];      // exp(states@Wsa + att_b)
__device__ __align__(16) __half g_T [M_TOTAL * 2 * CC];  // per node: [EL(128)|ELS(128)] fp16
__device__ __align__(16) __half g_Gh[M_TOTAL * CC];      // linked_gated, fp16
__device__ __align__(16) float  g_SS[M_TOTAL * CC];      // states / norm, fp32
__device__ int g_cur[M_TOTAL];
__device__ int g_adj[M_TOTAL * STRIDE];

// ---------------- ELL build ------------------------------------------------
__global__ void zero_cur_kernel() {
    int i = blockIdx.x * blockDim.x + threadIdx.x;
    if (i < M_TOTAL) g_cur[i] = 0;
}

__global__ void fill_kernel(const int* __restrict__ conn) {
    int idx = blockIdx.x * blockDim.x + threadIdx.x;
    if (idx >= BB * EE) return;
    int b = idx / EE;
    int2 uv = ((const int2*)conn)[idx];
    int nu = b * NN + uv.x, nv = b * NN + uv.y;
    int p = atomicAdd(&g_cur[nu], 1);
    if (p < STRIDE) g_adj[(size_t)nu * STRIDE + p] = uv.y;
    int q = atomicAdd(&g_cur[nv], 1);
    if (q < STRIDE) g_adj[(size_t)nv * STRIDE + q] = uv.x;
}

// ---------------- mma.sync helpers -----------------------------------------
__device__ __forceinline__ unsigned smem_u32(const void* p) {
    return (unsigned)__cvta_generic_to_shared(p);
}

#define LDSM_X4(r, addr) \
    asm volatile("ldmatrix.sync.aligned.m8n8.x4.shared.b16 {%0,%1,%2,%3}, [%4];" \
                 : "=r"((r)[0]), "=r"((r)[1]), "=r"((r)[2]), "=r"((r)[3]) : "r"(addr))
#define LDSM_X4T(r, addr) \
    asm volatile("ldmatrix.sync.aligned.m8n8.x4.trans.shared.b16 {%0,%1,%2,%3}, [%4];" \
                 : "=r"((r)[0]), "=r"((r)[1]), "=r"((r)[2]), "=r"((r)[3]) : "r"(addr))
#define MMA16816(acc, a, b0, b1) \
    asm volatile("mma.sync.aligned.m16n8k16.row.col.f32.f16.f16.f32 " \
                 "{%0,%1,%2,%3}, {%4,%5,%6,%7}, {%8,%9}, {%0,%1,%2,%3};" \
                 : "+f"((acc)[0]), "+f"((acc)[1]), "+f"((acc)[2]), "+f"((acc)[3]) \
                 : "r"((a)[0]), "r"((a)[1]), "r"((a)[2]), "r"((a)[3]), "r"(b0), "r"(b1))

#define KSTEP_A (16 * 2)            // 16 halves along a row
#define KSTEP_B (16 * LDH * 2)      // 16 rows

// convert one fp32 128x128 weight matrix into fp16 smem (stride LDH)
__device__ __forceinline__ void load_W(const float* __restrict__ W, __half* Ws, int t) {
    const float4* W4 = (const float4*)W;
#pragma unroll
    for (int i = 0; i < 8; i++) {
        float4 v = W4[t + 512 * i];
        int e = (t + 512 * i) * 4;
        int r = e >> 7, c = e & 127;
        __half2* dst = (__half2*)&Ws[r * LDH + c];
        dst[0] = __floats2half2_rn(v.x, v.y);
        dst[1] = __floats2half2_rn(v.z, v.w);
    }
}

// ---------------- fused per-iteration GEMM kernel ---------------------------
// P1UPD=0: phase1 A = objects (fp32->fp16), out = tanh(A@Wp + stb)
// P1UPD=1: phase1 A = gathered G (fp16),    out = tanh(A@Wp + SS + stb)
// DO_ATTN: phase2 A = new states (fp16, smem), dual GEMM vs W1/W2 -> EA, T
template <int P1UPD, int DO_ATTN>
__global__ void __launch_bounds__(THREADS, 1)
fused_k(const float* __restrict__ Xf, const __half* __restrict__ Gh,
        const float* __restrict__ Wp, const float* __restrict__ stb,
        const float* __restrict__ SS,
        const float* __restrict__ W1, const float* __restrict__ W2,
        const float* __restrict__ attb,
        float* __restrict__ states, float* __restrict__ EA,
        __half* __restrict__ T)
{
    extern __shared__ __half sh[];
    __half* Wps = sh;
    __half* W1s = sh + CC * LDH;                       // DO_ATTN only
    __half* W2s = sh + 2 * CC * LDH;                   // DO_ATTN only
    __half* As  = sh + (DO_ATTN ? 3 : 1) * CC * LDH;   // TM x LDH
    __half* Ss  = As + TM * LDH;                       // DO_ATTN only
    int t = threadIdx.x;

    load_W(Wp, Wps, t);
    if (DO_ATTN) { load_W(W1, W1s, t); load_W(W2, W2s, t); }

    int lane = t & 31, wid = t >> 5;
    int wm = (wid & 3) * 16;
    int wn = (wid >> 2) * 32;
    unsigned a_base = smem_u32(&As[(wm + (lane & 15)) * LDH + ((lane >> 4) << 3)]);
    unsigned s_base = DO_ATTN ? smem_u32(&Ss[(wm + (lane & 15)) * LDH + ((lane >> 4) << 3)]) : 0u;
    int brow = ((lane >> 3) & 1) * 8 + (lane & 7);
    int bcol = wn + ((lane >> 4) << 3);
    unsigned bp_base = smem_u32(&Wps[brow * LDH + bcol]);
    unsigned b1_base = DO_ATTN ? smem_u32(&W1s[brow * LDH + bcol]) : 0u;
    unsigned b2_base = DO_ATTN ? smem_u32(&W2s[brow * LDH + bcol]) : 0u;
    int lr0 = wm + (lane >> 2);
    int col_in = (lane & 3) * 2;

    // preload first tile's raw phase-1 operand
    float4 rX[4];
    uint4  rG[2];
    int tile = blockIdx.x;
    if (tile < NTILES) {
        if (P1UPD == 0) {
            const float4* X4 = (const float4*)(Xf + (size_t)tile * TM * CC);
#pragma unroll
            for (int i = 0; i < 4; i++) rX[i] = X4[t + 512 * i];
        } else {
            const uint4* G4 = (const uint4*)(Gh + (size_t)tile * TM * CC);
#pragma unroll
            for (int i = 0; i < 2; i++) rG[i] = G4[t + 512 * i];
        }
    }

    for (; tile < NTILES; tile += PGRID) {
        __syncthreads();                        // As/Ss free from previous tile
        if (P1UPD == 0) {
#pragma unroll
            for (int i = 0; i < 4; i++) {
                int e = (t + 512 * i) * 4;
                int r = e >> 7, c = e & 127;
                __half2* dst = (__half2*)&As[r * LDH + c];
                dst[0] = __floats2half2_rn(rX[i].x, rX[i].y);
                dst[1] = __floats2half2_rn(rX[i].z, rX[i].w);
            }
        } else {
#pragma unroll
            for (int i = 0; i < 2; i++) {
                int e = (t + 512 * i) * 8;
                int r = e >> 7, c = e & 127;
                *(uint4*)&As[r * LDH + c] = rG[i];
            }
        }
        __syncthreads();

        // ---- phase 1 mainloop: As @ Wps -> acc
        float acc[4][4];
#pragma unroll
        for (int nf = 0; nf < 4; nf++)
#pragma unroll
            for (int q = 0; q < 4; q++) acc[nf][q] = 0.f;
        {
            unsigned a[2][4], b0[2][4], b1[2][4];
            LDSM_X4 (a[0],  a_base);
            LDSM_X4T(b0[0], bp_base);
            LDSM_X4T(b1[0], bp_base + 32);
#pragma unroll
            for (int ks = 0; ks < 8; ks++) {
                int cur = ks & 1, nxt = cur ^ 1;
                if (ks < 7) {
                    unsigned ao = a_base + (ks + 1) * KSTEP_A;
                    unsigned bo = bp_base + (ks + 1) * KSTEP_B;
                    LDSM_X4 (a[nxt],  ao);
                    LDSM_X4T(b0[nxt], bo);
                    LDSM_X4T(b1[nxt], bo + 32);
                }
                MMA16816(acc[0], a[cur], b0[cur][0], b0[cur][1]);
                MMA16816(acc[1], a[cur], b0[cur][2], b0[cur][3]);
                MMA16816(acc[2], a[cur], b1[cur][0], b1[cur][1]);
                MMA16816(acc[3], a[cur], b1[cur][2], b1[cur][3]);
            }
        }

        // preload next tile's raw operand (hides under epilogues/phase2)
        int next = tile + PGRID;
        if (next < NTILES) {
            if (P1UPD == 0) {
                const float4* X4 = (const float4*)(Xf + (size_t)next * TM * CC);
#pragma unroll
                for (int i = 0; i < 4; i++) rX[i] = X4[t + 512 * i];
            } else {
                const uint4* G4 = (const uint4*)(Gh + (size_t)next * TM * CC);
#pragma unroll
                for (int i = 0; i < 2; i++) rG[i] = G4[t + 512 * i];
            }
        }

        // ---- phase 1 epilogue: states = tanh(acc [+SS] + stb)
        int block_row = tile * TM;
#pragma unroll
        for (int nf = 0; nf < 4; nf++) {
            int col = wn + nf * 8 + col_in;
#pragma unroll
            for (int half = 0; half < 2; half++) {
                int lrow = lr0 + half * 8;
                size_t grow = (size_t)(block_row + lrow);
                float v0 = acc[nf][half * 2 + 0];
                float v1 = acc[nf][half * 2 + 1];
                float2 bz = *(const float2*)&stb[col];
                if (P1UPD == 1) {
                    float2 ad = *(const float2*)&SS[grow * CC + col];
                    v0 += ad.x; v1 += ad.y;
                }
                float s0 = tanhf(v0 + bz.x);
                float s1 = tanhf(v1 + bz.y);
                float2 o; o.x = s0; o.y = s1;
                *(float2*)&states[grow * CC + col] = o;
                if (DO_ATTN)
                    *(__half2*)&Ss[lrow * LDH + col] = __floats2half2_rn(s0, s1);
            }
        }

        if (DO_ATTN) {
            __syncthreads();                    // Ss tile complete

            // ---- phase 2 mainloop: Ss @ (W1s, W2s) -> accE, accL
            float accE[4][4], accL[4][4];
#pragma unroll
            for (int nf = 0; nf < 4; nf++)
#pragma unroll
                for (int q = 0; q < 4; q++) { accE[nf][q] = 0.f; accL[nf][q] = 0.f; }
            {
                unsigned a[2][4], bE0[2][4], bE1[2][4], bL0[2][4], bL1[2][4];
                LDSM_X4 (a[0],   s_base);
                LDSM_X4T(bE0[0], b1_base);
                LDSM_X4T(bE1[0], b1_base + 32);
                LDSM_X4T(bL0[0], b2_base);
                LDSM_X4T(bL1[0], b2_base + 32);
#pragma unroll
                for (int ks = 0; ks < 8; ks++) {
                    int cur = ks & 1, nxt = cur ^ 1;
                    if (ks < 7) {
                        unsigned ao  = s_base  + (ks + 1) * KSTEP_A;
                        unsigned b1o = b1_base + (ks + 1) * KSTEP_B;
                        unsigned b2o = b2_base + (ks + 1) * KSTEP_B;
                        LDSM_X4 (a[nxt],   ao);
                        LDSM_X4T(bE0[nxt], b1o);
                        LDSM_X4T(bE1[nxt], b1o + 32);
                        LDSM_X4T(bL0[nxt], b2o);
                        LDSM_X4T(bL1[nxt], b2o + 32);
                    }
                    MMA16816(accE[0], a[cur], bE0[cur][0], bE0[cur][1]);
                    MMA16816(accE[1], a[cur], bE0[cur][2], bE0[cur][3]);
                    MMA16816(accE[2], a[cur], bE1[cur][0], bE1[cur][1]);
                    MMA16816(accE[3], a[cur], bE1[cur][2], bE1[cur][3]);
                    MMA16816(accL[0], a[cur], bL0[cur][0], bL0[cur][1]);
                    MMA16816(accL[1], a[cur], bL0[cur][2], bL0[cur][3]);
                    MMA16816(accL[2], a[cur], bL1[cur][0], bL1[cur][1]);
                    MMA16816(accL[3], a[cur], bL1[cur][2], bL1[cur][3]);
                }
            }

            // ---- phase 2 epilogue: EA fp32, T = [EL|ELS] fp16
#pragma unroll
            for (int nf = 0; nf < 4; nf++) {
                int col = wn + nf * 8 + col_in;
#pragma unroll
                for (int half = 0; half < 2; half++) {
                    int lrow = lr0 + half * 8;
                    size_t grow = (size_t)(block_row + lrow);
                    float2 bz = *(const float2*)&attb[col];
                    float2 oe;
                    oe.x = __expf(accE[nf][half * 2 + 0] + bz.x);
                    oe.y = __expf(accE[nf][half * 2 + 1] + bz.y);
                    *(float2*)&EA[grow * CC + col] = oe;
                    float el0 = __expf(accL[nf][half * 2 + 0]);
                    float el1 = __expf(accL[nf][half * 2 + 1]);
                    float s0 = __half2float(Ss[lrow * LDH + col]);
                    float s1 = __half2float(Ss[lrow * LDH + col + 1]);
                    *(__half2*)&T[grow * 2 * CC + col]      = __floats2half2_rn(el0, el1);
                    *(__half2*)&T[grow * 2 * CC + CC + col] = __floats2half2_rn(el0 * s0, el1 * s1);
                }
            }
        }
    }
}

// ---------------- per-node aggregation (one warp per node, no atomics) -----
__device__ __forceinline__ void acc8_fp16(float* acc, uint4 v) {
    unsigned int u[4] = {v.x, v.y, v.z, v.w};
#pragma unroll
    for (int q = 0; q < 4; q++) {
        float2 f = __half22float2(*(__half2*)&u[q]);
        acc[2 * q]     += f.x;
        acc[2 * q + 1] += f.y;
    }
}

__global__ void agg_kernel(const float* __restrict__ states) {
    int gw = (blockIdx.x * blockDim.x + threadIdx.x) >> 5;
    int lane = threadIdx.x & 31;
    if (gw >= M_TOTAL) return;
    int b = gw / NN;

    int deg = g_cur[gw];
    if (deg > STRIDE) deg = STRIDE;
    const int* __restrict__ adj = g_adj + (size_t)gw * STRIDE;
    const uint4* __restrict__ T4 = (const uint4*)(g_T + (size_t)b * NN * 2 * CC);

    float acc[8];
#pragma unroll
    for (int k = 0; k < 8; k++) acc[k] = 0.f;

    int e = 0;
    for (; e + 4 <= deg; e += 4) {
        int j0 = __ldg(adj + e);
        int j1 = __ldg(adj + e + 1);
        int j2 = __ldg(adj + e + 2);
        int j3 = __ldg(adj + e + 3);
        uint4 t0 = T4[(size_t)j0 * 32 + lane];
        uint4 t1 = T4[(size_t)j1 * 32 + lane];
        uint4 t2 = T4[(size_t)j2 * 32 + lane];
        uint4 t3 = T4[(size_t)j3 * 32 + lane];
        acc8_fp16(acc, t0);
        acc8_fp16(acc, t1);
        acc8_fp16(acc, t2);
        acc8_fp16(acc, t3);
    }
    for (; e < deg; e++) {
        int j = __ldg(adj + e);
        uint4 tv = T4[(size_t)j * 32 + lane];
        acc8_fp16(acc, tv);
    }

    float other[8];
#pragma unroll
    for (int k = 0; k < 8; k++)
        other[k] = __shfl_xor_sync(0xffffffffu, acc[k], 16);

    int sub = lane & 15;
    size_t rowf4 = (size_t)gw * 32 + sub * 2;
    float4 ea0 = ((const float4*)g_EA)[rowf4];
    float4 ea1 = ((const float4*)g_EA)[rowf4 + 1];
    float ea[8] = {ea0.x, ea0.y, ea0.z, ea0.w, ea1.x, ea1.y, ea1.z, ea1.w};

    float sE[8], sS[8];
    if (lane < 16) {
#pragma unroll
        for (int k = 0; k < 8; k++) { sE[k] = acc[k]; sS[k] = other[k]; }
    } else {
#pragma unroll
        for (int k = 0; k < 8; k++) { sE[k] = other[k]; sS[k] = acc[k]; }
    }

    float inv[8];
#pragma unroll
    for (int k = 0; k < 8; k++) inv[k] = 1.f / (1.f + ea[k] * sE[k]);

    if (lane < 16) {
        // G = ea * sS * inv  -> fp16 (same convert previously done at gemm3 stash)
        __half2 h[4];
#pragma unroll
        for (int q = 0; q < 4; q++)
            h[q] = __floats2half2_rn(ea[2 * q] * sS[2 * q] * inv[2 * q],
                                     ea[2 * q + 1] * sS[2 * q + 1] * inv[2 * q + 1]);
        *(uint4*)&g_Gh[(size_t)gw * CC + sub * 8] = *(uint4*)h;
    } else {
        float4 st0 = ((const float4*)states)[rowf4];
        float4 st1 = ((const float4*)states)[rowf4 + 1];
        float4 S0, S1;
        S0.x = st0.x * inv[0]; S0.y = st0.y * inv[1];
        S0.z = st0.z * inv[2]; S0.w = st0.w * inv[3];
        S1.x = st1.x * inv[4]; S1.y = st1.y * inv[5];
        S1.z = st1.z * inv[6]; S1.w = st1.w * inv[7];
        ((float4*)g_SS)[rowf4]     = S0;
        ((float4*)g_SS)[rowf4 + 1] = S1;
    }
}

// ---------------- launch ----------------------------------------------------
extern "C" void kernel_launch(void* const* d_in, const int* in_sizes, int n_in,
                              void* d_out, int out_size) {
    const float* objects = (const float*)d_in[0];
    const float* Wos     = (const float*)d_in[1];
    const float* Wsa     = (const float*)d_in[2];
    const float* Wla     = (const float*)d_in[3];
    const float* att_b   = (const float*)d_in[4];
    const float* Wl      = (const float*)d_in[5];
    const float* st_b    = (const float*)d_in[6];
    const int*   conn    = (const int*)d_in[7];
    float* states = (float*)d_out;            // live states buffer, [B,N,C]

    cudaFuncSetAttribute((const void*)fused_k<0, 1>,
                         cudaFuncAttributeMaxDynamicSharedMemorySize, SM_FULL);
    cudaFuncSetAttribute((const void*)fused_k<1, 1>,
                         cudaFuncAttributeMaxDynamicSharedMemorySize, SM_FULL);
    cudaFuncSetAttribute((const void*)fused_k<1, 0>,
                         cudaFuncAttributeMaxDynamicSharedMemorySize, SM_UPD);

    float *pEA, *pSS;
    __half *pT, *pGh;
    cudaGetSymbolAddress((void**)&pEA, g_EA);
    cudaGetSymbolAddress((void**)&pT,  g_T);
    cudaGetSymbolAddress((void**)&pGh, g_Gh);
    cudaGetSymbolAddress((void**)&pSS, g_SS);

    const int EDGE_BLOCKS = (BB * EE + 255) / 256;      // 2500
    const int AGG_GRID    = (M_TOTAL * 32 + 255) / 256; // 5000

    // ELL build (per launch; connections are an input)
    zero_cur_kernel<<<(M_TOTAL + 255) / 256, 256>>>();
    fill_kernel<<<EDGE_BLOCKS, 256>>>(conn);

    // init: states = tanh(objects@Wos + st_b), then EA + T from new states
    fused_k<0, 1><<<PGRID, THREADS, SM_FULL>>>(objects, nullptr, Wos, st_b, nullptr,
                                               Wsa, Wla, att_b, states, pEA, pT);

    for (int it = 0; it < ITERS; it++) {
        agg_kernel<<<AGG_GRID, 256>>>(states);
        if (it < ITERS - 1) {
            // update + attention for next iteration
            fused_k<1, 1><<<PGRID, THREADS, SM_FULL>>>(nullptr, pGh, Wl, st_b, pSS,
                                                       Wsa, Wla, att_b, states, pEA, pT);
        } else {
            // final update only
            fused_k<1, 0><<<PGRID, THREADS, SM_UPD>>>(nullptr, pGh, Wl, st_b, pSS,
                                                      nullptr, nullptr, nullptr,
                                                      states, nullptr, nullptr);
        }
    }
}